// round 8
// baseline (speedup 1.0000x reference)
#include <cuda_runtime.h>

#define BB 8
#define NN 2048
#define NH 8
#define MAT 16384
#define SCALE (1.0f/16384.0f)   // 1/(N*NH)

// ---------------- scratch (device globals) ----------------
__device__ __align__(16) float g_part[16 * BB * MAT];
__device__ __align__(16) float g_G[2][BB * MAT];
__device__ __align__(16) float g_R [BB * MAT];
__device__ __align__(16) float g_Wp[BB * NH * MAT];
__device__ __align__(16) float g_Wq[BB * MAT];
__device__ __align__(16) float g_U [BB * MAT];

// ---------------- tf32 helpers ----------------
__device__ __forceinline__ float tf(float x) {
    float y; asm("cvt.rna.tf32.f32 %0, %1;" : "=f"(y) : "f"(x)); return y;
}
__device__ __forceinline__ float4 tf4(float4 x) {
    x.x = tf(x.x); x.y = tf(x.y); x.z = tf(x.z); x.w = tf(x.w); return x;
}
// NOTE: not volatile — pure register computation, lets ptxas pipeline LDS across MMAs
__device__ __forceinline__ void mma8(float c[4], const float* a, const float* b) {
    asm("mma.sync.aligned.m16n8k8.row.col.f32.tf32.tf32.f32 "
        "{%0,%1,%2,%3}, {%4,%5,%6,%7}, {%8,%9}, {%0,%1,%2,%3};"
        : "+f"(c[0]), "+f"(c[1]), "+f"(c[2]), "+f"(c[3])
        : "r"(__float_as_uint(a[0])), "r"(__float_as_uint(a[1])),
          "r"(__float_as_uint(a[2])), "r"(__float_as_uint(a[3])),
          "r"(__float_as_uint(b[0])), "r"(__float_as_uint(b[1])));
}

// ============================================================================
// Fragment-ordered smem layouts.
// A-frag: frag = mblk*16 + kblk  (mblk = m/16, kblk = k/8)
//   float As[frag][32 lanes][4 slots];  lane = (m&7)*4 + (k&3)
//   slot  = ((m>>3)&1) + 2*((k>>2)&1)
//   -> per-fragment load = one LDS.128 (lane-contiguous)
// B-frag: frag = kblk*16 + nblk  (kblk = k/8, nblk = n/8)
//   float Bs[frag][32 lanes][2 slots];  lane = (n&7)*4 + (k&3)
//   slot  = (k>>2)&1
//   -> per-fragment load = one LDS.64
// ============================================================================

// ---- A fills (row-major source: As[m][k] = tf(A[m*lda+k])) ----
template<int MROWS>
__device__ __forceinline__ void fillA_frag(const float* __restrict__ A, int lda,
                                           float* __restrict__ As) {
#pragma unroll
    for (int i = 0; i < MROWS / 16; i++) {
        int idx = threadIdx.x + 512 * i;
        int m = idx >> 5, k = (idx & 31) * 4;
        float4 x = tf4(*(const float4*)(A + m * lda + k));
        int frag = (m >> 4) * 16 + (k >> 3);
        float* p = As + (frag << 7) + ((k >> 2) & 1) * 2 + ((m >> 3) & 1);
        int l0 = (m & 7) * 16;           // lane*4 base; lane = (m&7)*4 + i2
        p[l0]      = x.x;
        p[l0 + 4]  = x.y;
        p[l0 + 8]  = x.z;
        p[l0 + 12] = x.w;
    }
}
// ---- A fills (transposed source: As[m][k] = tf(A[k*lda + moff + m])) ----
// MROWS=128: k=idx>>5, m=(idx&31)*4 ; MROWS=64: k=idx>>4, m=(idx&15)*4
template<int MROWS>
__device__ __forceinline__ void fillAT_frag(const float* __restrict__ A, int lda,
                                            int moff, float* __restrict__ As) {
#pragma unroll
    for (int i = 0; i < MROWS / 16; i++) {
        int idx = threadIdx.x + 512 * i;
        int k, m;
        if (MROWS == 128) { k = idx >> 5; m = (idx & 31) * 4; }
        else              { k = idx >> 4; m = (idx & 15) * 4; }
        float4 x = tf4(*(const float4*)(A + k * lda + moff + m));
        int frag = (m >> 4) * 16 + (k >> 3);
        int slot = ((m >> 3) & 1) + ((k >> 2) & 1) * 2;
        float* p = As + (frag << 7) + (k & 3) * 4 + slot;
        int l0 = (m & 7) * 16;           // lane = ((m&7)+i2)*4 + (k&3)
        p[l0]      = x.x;
        p[l0 + 16] = x.y;
        p[l0 + 32] = x.z;
        p[l0 + 48] = x.w;
    }
}
// ---- B fill (row-major source: Bs[k][n] = tf(B[k*ldb+n])) ----
__device__ __forceinline__ void fillB_frag(const float* __restrict__ B, int ldb,
                                           float* __restrict__ Bs) {
#pragma unroll
    for (int i = 0; i < 8; i++) {
        int idx = threadIdx.x + 512 * i;
        int k = idx >> 5, n = (idx & 31) * 4;
        float4 x = tf4(*(const float4*)(B + k * ldb + n));
        int frag = (k >> 3) * 16 + (n >> 3);
        float* p = Bs + (frag << 6) + (k & 3) * 2 + ((k >> 2) & 1);
        int l0 = (n & 7) * 8;            // lane = ((n&7)+i2)*4 + (k&3)
        p[l0]      = x.x;
        p[l0 + 8]  = x.y;
        p[l0 + 16] = x.z;
        p[l0 + 24] = x.w;
    }
}
// ---- B fill, sum of two sources ----
__device__ __forceinline__ void fillB2_frag(const float* __restrict__ B1,
                                            const float* __restrict__ B2,
                                            float* __restrict__ Bs) {
#pragma unroll
    for (int i = 0; i < 8; i++) {
        int idx = threadIdx.x + 512 * i;
        int k = idx >> 5, n = (idx & 31) * 4;
        float4 x = *(const float4*)(B1 + k * 128 + n);
        float4 y = *(const float4*)(B2 + k * 128 + n);
        x.x += y.x; x.y += y.y; x.z += y.z; x.w += y.w;
        x = tf4(x);
        int frag = (k >> 3) * 16 + (n >> 3);
        float* p = Bs + (frag << 6) + (k & 3) * 2 + ((k >> 2) & 1);
        int l0 = (n & 7) * 8;
        p[l0]      = x.x;
        p[l0 + 8]  = x.y;
        p[l0 + 16] = x.z;
        p[l0 + 24] = x.w;
    }
}
// ---- B fill (transposed source: Bs[k][n] = tf(B[n*ldb+k])) — V^T ----
__device__ __forceinline__ void fillBT_frag(const float* __restrict__ B, int ldb,
                                            float* __restrict__ Bs) {
#pragma unroll
    for (int i = 0; i < 8; i++) {
        int idx = threadIdx.x + 512 * i;
        int n = idx >> 5, k = (idx & 31) * 4;
        float4 x = tf4(*(const float4*)(B + n * ldb + k));
        int frag = (k >> 3) * 16 + (n >> 3);
        float* p = Bs + (frag << 6) + (n & 7) * 8 + ((k >> 2) & 1);
        p[0] = x.x;                      // lane = (n&7)*4 + i2
        p[2] = x.y;
        p[4] = x.z;
        p[6] = x.w;
    }
}

// ---------------- compute cores ----------------
__device__ __forceinline__ void compute128(const float* __restrict__ As,
                                           const float* __restrict__ Bs,
                                           float acc[2][4][4]) {
    const float4* Af = (const float4*)As;
    const float2* Bf = (const float2*)Bs;
    const int lane = threadIdx.x & 31, warp = threadIdx.x >> 5;
    const int mb = (warp & 3) * 2, nb = (warp >> 2) * 4;
#pragma unroll
    for (int kb = 0; kb < 16; kb++) {
        float4 a0 = Af[(mb * 16 + kb) * 32 + lane];
        float4 a1 = Af[((mb + 1) * 16 + kb) * 32 + lane];
#pragma unroll
        for (int j = 0; j < 4; j++) {
            float2 b = Bf[(kb * 16 + nb + j) * 32 + lane];
            mma8(acc[0][j], &a0.x, &b.x);
            mma8(acc[1][j], &a1.x, &b.x);
        }
    }
}
__device__ __forceinline__ void compute64(const float* __restrict__ As,
                                          const float* __restrict__ Bs,
                                          float acc[4][4]) {
    const float4* Af = (const float4*)As;
    const float2* Bf = (const float2*)Bs;
    const int lane = threadIdx.x & 31, warp = threadIdx.x >> 5;
    const int mb = warp & 3, nb = (warp >> 2) * 4;
#pragma unroll
    for (int kb = 0; kb < 16; kb++) {
        float4 a = Af[(mb * 16 + kb) * 32 + lane];
#pragma unroll
        for (int j = 0; j < 4; j++) {
            float2 b = Bf[(kb * 16 + nb + j) * 32 + lane];
            mma8(acc[j], &a.x, &b.x);
        }
    }
}

// ---------------- epilogues (write row-major global, ld=128) ----------------
__device__ __forceinline__ void epi128(float* __restrict__ C,
                                       const float* __restrict__ a1,
                                       float acc[2][4][4]) {
    const int lane = threadIdx.x & 31, warp = threadIdx.x >> 5;
    const int r0 = (warp & 3) * 32 + (lane >> 2);
    const int c0 = (warp >> 2) * 32 + 2 * (lane & 3);
#pragma unroll
    for (int i = 0; i < 2; i++)
#pragma unroll
        for (int j = 0; j < 4; j++) {
            int r = r0 + 16 * i, c = c0 + 8 * j;
            float2 lo = make_float2(acc[i][j][0], acc[i][j][1]);
            float2 hi = make_float2(acc[i][j][2], acc[i][j][3]);
            if (a1) {
                float2 x = *(const float2*)(a1 + r * 128 + c);
                float2 y = *(const float2*)(a1 + (r + 8) * 128 + c);
                lo.x += x.x; lo.y += x.y; hi.x += y.x; hi.y += y.y;
            }
            *(float2*)(C + r * 128 + c)       = lo;
            *(float2*)(C + (r + 8) * 128 + c) = hi;
        }
}
__device__ __forceinline__ void epi64(float* __restrict__ C,
                                      const float* __restrict__ a1,
                                      const float* __restrict__ a2,
                                      float acc[4][4]) {
    const int lane = threadIdx.x & 31, warp = threadIdx.x >> 5;
    const int r0 = (warp & 3) * 16 + (lane >> 2);
    const int c0 = (warp >> 2) * 32 + 2 * (lane & 3);
#pragma unroll
    for (int j = 0; j < 4; j++) {
        int c = c0 + 8 * j;
        float2 lo = make_float2(acc[j][0], acc[j][1]);
        float2 hi = make_float2(acc[j][2], acc[j][3]);
        if (a1) {
            float2 x = *(const float2*)(a1 + r0 * 128 + c);
            float2 y = *(const float2*)(a1 + (r0 + 8) * 128 + c);
            lo.x += x.x; lo.y += x.y; hi.x += y.x; hi.y += y.y;
        }
        if (a2) {
            float2 x = *(const float2*)(a2 + r0 * 128 + c);
            float2 y = *(const float2*)(a2 + (r0 + 8) * 128 + c);
            lo.x += x.x; lo.y += x.y; hi.x += y.x; hi.y += y.y;
        }
        *(float2*)(C + r0 * 128 + c)       = lo;
        *(float2*)(C + (r0 + 8) * 128 + c) = hi;
    }
}
// T (64x128 warp-tiled acc) -> A-fragment-order smem (tf32), for chained GEMM.
// Output element (r,c): r in {r0, r0+8}+mr, c = nc + 8j + 2q + d.
__device__ __forceinline__ void storeT64_frag(float* __restrict__ As,
                                              float acc[4][4]) {
    const int lane = threadIdx.x & 31, warp = threadIdx.x >> 5;
    const int r = lane >> 2, q = lane & 3;
    const int c3b = 2 * (q & 1);       // (2q)&3
    const int s2  = 2 * (q >> 1);      // 2*((2q)>>2)
#pragma unroll
    for (int j = 0; j < 4; j++) {
        float* base = As + ((((warp & 3) * 16) + (warp >> 2) * 4 + j) << 7);
        base[(r * 4 + c3b)     * 4 + s2]     = tf(acc[j][0]);
        base[(r * 4 + c3b + 1) * 4 + s2]     = tf(acc[j][1]);
        base[(r * 4 + c3b)     * 4 + s2 + 1] = tf(acc[j][2]);
        base[(r * 4 + c3b + 1) * 4 + s2 + 1] = tf(acc[j][3]);
    }
}
__device__ __forceinline__ void zero4(float a[4][4]) {
#pragma unroll
    for (int j = 0; j < 4; j++)
#pragma unroll
        for (int r = 0; r < 4; r++) a[j][r] = 0.0f;
}

// ---------------- kernels ----------------
#define AF128 16384
#define AF64   8192
#define BF    16384

// part[chunk,b] = Zc^T @ Zc
__global__ __launch_bounds__(512) void k_g0(const float* __restrict__ Z,
                                            float* __restrict__ part) {
    extern __shared__ float sm[];
    float* As = sm; float* Bs = sm + AF128;
    int chunk = blockIdx.x, b = blockIdx.y;
    const float* Zc = Z + (b * NN + chunk * 128) * 128;
    fillAT_frag<128>(Zc, 128, 0, As);
    fillB_frag(Zc, 128, Bs);
    __syncthreads();
    float acc[2][4][4]; zero4(acc[0]); zero4(acc[1]);
    compute128(As, Bs, acc);
    epi128(part + (chunk * BB + b) * MAT, 0, acc);
}

__global__ __launch_bounds__(512) void k_greduce(const float* __restrict__ part,
                                                 float* __restrict__ G) {
    int e = blockIdx.x * 512 + threadIdx.x;   // 131072
    int b = e >> 14, i = e & 16383;
    float s = 0.0f;
#pragma unroll
    for (int c = 0; c < 16; c++) s += part[(c * BB + b) * MAT + i];
    G[e] = s;
}

// fused T = Q@G then W = T@V^T, 64-row half per block. grid (j, b, mh)
__global__ __launch_bounds__(512) void k_TW(const float* __restrict__ q,
                                            const float* __restrict__ v,
                                            const float* __restrict__ G,
                                            float* __restrict__ Wp, int l) {
    extern __shared__ float sm[];
    float* As  = sm;
    float* BsG = sm + AF64;
    float* BsV = BsG + BF;
    int j = blockIdx.x, b = blockIdx.y, mh = blockIdx.z;
    fillA_frag<64>(q + (l * NH + j) * MAT + mh * 64 * 128, 128, As);
    fillB_frag(G + b * MAT, 128, BsG);
    fillBT_frag(v + (l * NH + j) * MAT, 128, BsV);
    __syncthreads();
    float acc[4][4]; zero4(acc);
    compute64(As, BsG, acc);
    __syncthreads();                 // all reads of Q done
    storeT64_frag(As, acc);
    __syncthreads();
    zero4(acc);
    compute64(As, BsV, acc);
    epi64(Wp + (b * NH + j) * MAT + mh * 64 * 128, 0, 0, acc);
}

// W'[b] = SCALE * sum_j Wp[b,j]; layer 0 also R = W'
__global__ __launch_bounds__(512) void k_Wsum(const float* __restrict__ Wp,
                                              float* __restrict__ Wq,
                                              float* __restrict__ R, int copyR) {
    int e = blockIdx.x * 512 + threadIdx.x;   // 131072
    int b = e >> 14, i = e & 16383;
    float s = 0.0f;
#pragma unroll
    for (int j = 0; j < NH; j++) s += Wp[(b * NH + j) * MAT + i];
    s *= SCALE;
    Wq[e] = s;
    if (copyR) R[e] = s;
}

// mode 0: U only; mode 1: z=0 -> U, z=1 -> R; mode 2: R only
// U slab = G @ W'; R slab = R + W' + R @ W'
__global__ __launch_bounds__(512) void k_RU(const float* __restrict__ G,
                                            float* __restrict__ R,
                                            const float* __restrict__ Wq,
                                            float* __restrict__ U, int mode) {
    extern __shared__ float sm[];
    float* As = sm; float* Bs = sm + AF64;
    int mh = blockIdx.x, b = blockIdx.y;
    int which = (mode == 2) ? 1 : blockIdx.z;
    const float* Ap = (which ? R : G) + b * MAT + mh * 64 * 128;
    fillA_frag<64>(Ap, 128, As);
    fillB_frag(Wq + b * MAT, 128, Bs);
    __syncthreads();
    float acc[4][4]; zero4(acc);
    compute64(As, Bs, acc);
    if (which) epi64(R + b * MAT + mh * 64 * 128,
                     R + b * MAT + mh * 64 * 128,
                     Wq + b * MAT + mh * 64 * 128, acc);
    else       epi64(U + b * MAT + mh * 64 * 128, 0, 0, acc);
}

// Gnext slab = W'^T slab @ (G+U) + G + U    grid (mh, b)
__global__ __launch_bounds__(512) void k_Gn(const float* __restrict__ Wq,
                                            const float* __restrict__ G,
                                            const float* __restrict__ U,
                                            float* __restrict__ Gn) {
    extern __shared__ float sm[];
    float* As = sm; float* Bs = sm + AF64;
    int mh = blockIdx.x, b = blockIdx.y;
    fillAT_frag<64>(Wq + b * MAT, 128, mh * 64, As);
    fillB2_frag(G + b * MAT, U + b * MAT, Bs);
    __syncthreads();
    float acc[4][4]; zero4(acc);
    compute64(As, Bs, acc);
    epi64(Gn + b * MAT + mh * 64 * 128,
          G  + b * MAT + mh * 64 * 128,
          U  + b * MAT + mh * 64 * 128, acc);
}

// out tile = Z_tile @ R + Z_tile    grid (tile16, b)
__global__ __launch_bounds__(512) void k_out(const float* __restrict__ Z,
                                             const float* __restrict__ R,
                                             float* __restrict__ out) {
    extern __shared__ float sm[];
    float* As = sm; float* Bs = sm + AF128;
    int tile = blockIdx.x, b = blockIdx.y;
    const float* Zt = Z + (b * NN + tile * 128) * 128;
    fillA_frag<128>(Zt, 128, As);
    fillB_frag(R + b * MAT, 128, Bs);
    __syncthreads();
    float acc[2][4][4]; zero4(acc[0]); zero4(acc[1]);
    compute128(As, Bs, acc);
    epi128(out + (b * NN + tile * 128) * 128, Zt, acc);
}

// ---------------- host ----------------
#define SZ_BIG ((AF128 + BF) * 4)          // 128 KB
#define SZ_TW  ((AF64 + 2 * BF) * 4)       // 160 KB
#define SZ_SM  ((AF64 + BF) * 4)           // 96 KB

extern "C" void kernel_launch(void* const* d_in, const int* in_sizes, int n_in,
                              void* d_out, int out_size) {
    const float* Z = (const float*)d_in[0];
    const float* v = (const float*)d_in[1];
    const float* q = (const float*)d_in[2];
    float* out = (float*)d_out;

    cudaFuncSetAttribute(k_g0,  cudaFuncAttributeMaxDynamicSharedMemorySize, SZ_BIG);
    cudaFuncSetAttribute(k_out, cudaFuncAttributeMaxDynamicSharedMemorySize, SZ_BIG);
    cudaFuncSetAttribute(k_TW,  cudaFuncAttributeMaxDynamicSharedMemorySize, SZ_TW);
    cudaFuncSetAttribute(k_RU,  cudaFuncAttributeMaxDynamicSharedMemorySize, SZ_SM);
    cudaFuncSetAttribute(k_Gn,  cudaFuncAttributeMaxDynamicSharedMemorySize, SZ_SM);

    float *pPart, *pG, *pR, *pWp, *pWq, *pU;
    cudaGetSymbolAddress((void**)&pPart, g_part);
    cudaGetSymbolAddress((void**)&pG,  g_G);
    cudaGetSymbolAddress((void**)&pR,  g_R);
    cudaGetSymbolAddress((void**)&pWp, g_Wp);
    cudaGetSymbolAddress((void**)&pWq, g_Wq);
    cudaGetSymbolAddress((void**)&pU,  g_U);

    float* Gbuf[2] = { pG, pG + BB * MAT };

    k_g0<<<dim3(16, BB), 512, SZ_BIG>>>(Z, pPart);
    k_greduce<<<256, 512>>>(pPart, Gbuf[0]);

    int cur = 0;
    for (int l = 0; l < 4; l++) {
        k_TW<<<dim3(NH, BB, 2), 512, SZ_TW>>>(q, v, Gbuf[cur], pWp, l);
        k_Wsum<<<256, 512>>>(pWp, pWq, pR, l == 0 ? 1 : 0);
        int mode = (l == 0) ? 0 : (l == 3) ? 2 : 1;
        int zz   = (mode == 1) ? 2 : 1;
        k_RU<<<dim3(2, BB, zz), 512, SZ_SM>>>(Gbuf[cur], pR, pWq, pU, mode);
        if (l < 3) {
            k_Gn<<<dim3(2, BB), 512, SZ_SM>>>(pWq, Gbuf[cur], pU, Gbuf[cur ^ 1]);
            cur ^= 1;
        }
    }

    k_out<<<dim3(16, BB), 512, SZ_BIG>>>(Z, pR, out);
}

// round 9
// speedup vs baseline: 1.5176x; 1.5176x over previous
#include <cuda_runtime.h>

#define BB 8
#define NN 2048
#define NH 8
#define MAT 16384
#define SCALE (1.0f/16384.0f)   // 1/(N*NH)
#define SA  132                 // A smem row stride (floats)
#define SBN 136                 // B smem row stride (floats)
#define SMF (64 * SA + 128 * SBN)      // 25856 floats
#define SZB (SMF * 4)                  // 103424 bytes — uniform for ALL kernels

// ---------------- scratch (device globals) ----------------
__device__ __align__(16) float g_part[16 * BB * MAT];
__device__ __align__(16) float g_G[2][BB * MAT];
__device__ __align__(16) float g_R [BB * MAT];
__device__ __align__(16) float g_Wp[BB * NH * MAT];
__device__ __align__(16) float g_U [BB * MAT];

// ---------------- tf32 helpers ----------------
__device__ __forceinline__ float tf(float x) {
    float y; asm("cvt.rna.tf32.f32 %0, %1;" : "=f"(y) : "f"(x)); return y;
}
__device__ __forceinline__ float4 tf4(float4 x) {
    x.x = tf(x.x); x.y = tf(x.y); x.z = tf(x.z); x.w = tf(x.w); return x;
}
__device__ __forceinline__ void mma8(float c[4], const float a[4], const float b[2]) {
    asm volatile(
        "mma.sync.aligned.m16n8k8.row.col.f32.tf32.tf32.f32 "
        "{%0,%1,%2,%3}, {%4,%5,%6,%7}, {%8,%9}, {%0,%1,%2,%3};"
        : "+f"(c[0]), "+f"(c[1]), "+f"(c[2]), "+f"(c[3])
        : "r"(__float_as_uint(a[0])), "r"(__float_as_uint(a[1])),
          "r"(__float_as_uint(a[2])), "r"(__float_as_uint(a[3])),
          "r"(__float_as_uint(b[0])), "r"(__float_as_uint(b[1])));
}

// ---------------- smem fills (512 threads; simple layout, R4-proven) ------
// As[m][k] = tf(A[m*lda + k]), 64 rows
__device__ __forceinline__ void fillA64(const float* __restrict__ A, int lda,
                                        float* __restrict__ As) {
#pragma unroll
    for (int i = 0; i < 4; i++) {
        int idx = threadIdx.x + 512 * i;
        int m = idx >> 5, kf = (idx & 31) * 4;
        *(float4*)(As + m * SA + kf) = tf4(*(const float4*)(A + m * lda + kf));
    }
}
// As[m][k] = tf(A[k*lda + moff + m])   (transposed source, 64 rows)
__device__ __forceinline__ void fillAT64(const float* __restrict__ A, int lda,
                                         int moff, float* __restrict__ As) {
#pragma unroll
    for (int i = 0; i < 4; i++) {
        int idx = threadIdx.x + 512 * i;
        int k = idx >> 4, mf = (idx & 15) * 4;
        float4 x = tf4(*(const float4*)(A + k * lda + moff + mf));
        As[(mf + 0) * SA + k] = x.x;
        As[(mf + 1) * SA + k] = x.y;
        As[(mf + 2) * SA + k] = x.z;
        As[(mf + 3) * SA + k] = x.w;
    }
}
// As[m][k] = tf(SCALE * sum_j Wp[j][k*128 + moff + m])  (W'^T slab, 64 rows)
__device__ __forceinline__ void fillAT64_ws(const float* __restrict__ Wpb,
                                            int moff, float* __restrict__ As) {
#pragma unroll
    for (int i = 0; i < 4; i++) {
        int idx = threadIdx.x + 512 * i;
        int k = idx >> 4, mf = (idx & 15) * 4;
        float4 s = make_float4(0.f, 0.f, 0.f, 0.f);
#pragma unroll
        for (int j = 0; j < 8; j++) {
            float4 x = *(const float4*)(Wpb + j * MAT + k * 128 + moff + mf);
            s.x += x.x; s.y += x.y; s.z += x.z; s.w += x.w;
        }
        As[(mf + 0) * SA + k] = tf(s.x * SCALE);
        As[(mf + 1) * SA + k] = tf(s.y * SCALE);
        As[(mf + 2) * SA + k] = tf(s.z * SCALE);
        As[(mf + 3) * SA + k] = tf(s.w * SCALE);
    }
}
// Bs[k][n] = tf(B[k*ldb + n]), 128x128
__device__ __forceinline__ void fillB(const float* __restrict__ B, int ldb,
                                      float* __restrict__ Bs) {
#pragma unroll
    for (int i = 0; i < 8; i++) {
        int idx = threadIdx.x + 512 * i;
        int k = idx >> 5, nf = (idx & 31) * 4;
        *(float4*)(Bs + k * SBN + nf) = tf4(*(const float4*)(B + k * ldb + nf));
    }
}
// Bs[k][n] = tf(SCALE * sum_j Wp[j][k*128+n])   (W' built in smem)
__device__ __forceinline__ void fillB_ws(const float* __restrict__ Wpb,
                                         float* __restrict__ Bs) {
#pragma unroll
    for (int i = 0; i < 8; i++) {
        int idx = threadIdx.x + 512 * i;
        int k = idx >> 5, nf = (idx & 31) * 4;
        float4 s = make_float4(0.f, 0.f, 0.f, 0.f);
#pragma unroll
        for (int j = 0; j < 8; j++) {
            float4 x = *(const float4*)(Wpb + j * MAT + k * 128 + nf);
            s.x += x.x; s.y += x.y; s.z += x.z; s.w += x.w;
        }
        s.x *= SCALE; s.y *= SCALE; s.z *= SCALE; s.w *= SCALE;
        *(float4*)(Bs + k * SBN + nf) = tf4(s);
    }
}
// Bs[k][n] = tf(B1[k*128+n] + B2[k*128+n])
__device__ __forceinline__ void fillB2(const float* __restrict__ B1,
                                       const float* __restrict__ B2,
                                       float* __restrict__ Bs) {
#pragma unroll
    for (int i = 0; i < 8; i++) {
        int idx = threadIdx.x + 512 * i;
        int k = idx >> 5, nf = (idx & 31) * 4;
        float4 x = *(const float4*)(B1 + k * 128 + nf);
        float4 y = *(const float4*)(B2 + k * 128 + nf);
        x.x += y.x; x.y += y.y; x.z += y.z; x.w += y.w;
        *(float4*)(Bs + k * SBN + nf) = tf4(x);
    }
}
// Bs[k][n] = tf(B[n*ldb + k])   (transposed: V^T)
__device__ __forceinline__ void fillBT(const float* __restrict__ B, int ldb,
                                       float* __restrict__ Bs) {
#pragma unroll
    for (int i = 0; i < 8; i++) {
        int idx = threadIdx.x + 512 * i;
        int n = idx >> 5, kf = (idx & 31) * 4;
        float4 x = tf4(*(const float4*)(B + n * ldb + kf));
        Bs[(kf + 0) * SBN + n] = x.x;
        Bs[(kf + 1) * SBN + n] = x.y;
        Bs[(kf + 2) * SBN + n] = x.z;
        Bs[(kf + 3) * SBN + n] = x.w;
    }
}

// ---------------- compute core: 64x128 tile, K=128, 16 warps --------------
__device__ __forceinline__ void compute64(const float* __restrict__ As,
                                          const float* __restrict__ Bs,
                                          float acc[4][4]) {
    const int lane = threadIdx.x & 31, warp = threadIdx.x >> 5;
    const int mr = (warp & 3) * 16, nc = (warp >> 2) * 32;
    const int ar = lane >> 2, ac = lane & 3;
    const int bk = lane & 3,  bn = lane >> 2;
#pragma unroll
    for (int kk = 0; kk < 128; kk += 8) {
        float a[4];
        const float* p = As + (mr + ar) * SA + kk + ac;
        a[0] = p[0]; a[1] = p[8 * SA]; a[2] = p[4]; a[3] = p[8 * SA + 4];
#pragma unroll
        for (int j = 0; j < 4; j++) {
            const float* qp = Bs + (kk + bk) * SBN + nc + 8 * j + bn;
            float b[2] = { qp[0], qp[4 * SBN] };
            mma8(acc[j], a, b);
        }
    }
}

// ---------------- epilogues ----------------
// adds: a1, a2 (global, optional), ws (smem full 128-row tile stride SBN,
// rows offset moff; optional — tf32-rounded W' add for R-update)
__device__ __forceinline__ void epi64(float* __restrict__ C,
                                      const float* __restrict__ a1,
                                      const float* __restrict__ a2,
                                      const float* __restrict__ ws, int moff,
                                      float acc[4][4]) {
    const int lane = threadIdx.x & 31, warp = threadIdx.x >> 5;
    const int r0 = (warp & 3) * 16 + (lane >> 2);
    const int c0 = (warp >> 2) * 32 + 2 * (lane & 3);
#pragma unroll
    for (int j = 0; j < 4; j++) {
        int c = c0 + 8 * j;
        float2 lo = make_float2(acc[j][0], acc[j][1]);
        float2 hi = make_float2(acc[j][2], acc[j][3]);
        if (a1) {
            float2 x = *(const float2*)(a1 + r0 * 128 + c);
            float2 y = *(const float2*)(a1 + (r0 + 8) * 128 + c);
            lo.x += x.x; lo.y += x.y; hi.x += y.x; hi.y += y.y;
        }
        if (a2) {
            float2 x = *(const float2*)(a2 + r0 * 128 + c);
            float2 y = *(const float2*)(a2 + (r0 + 8) * 128 + c);
            lo.x += x.x; lo.y += x.y; hi.x += y.x; hi.y += y.y;
        }
        if (ws) {
            lo.x += ws[(moff + r0) * SBN + c];
            lo.y += ws[(moff + r0) * SBN + c + 1];
            hi.x += ws[(moff + r0 + 8) * SBN + c];
            hi.y += ws[(moff + r0 + 8) * SBN + c + 1];
        }
        *(float2*)(C + r0 * 128 + c)       = lo;
        *(float2*)(C + (r0 + 8) * 128 + c) = hi;
    }
}
// acc (64x128 warp-tiled) -> As simple layout (tf32), for chained GEMM
__device__ __forceinline__ void storeT64(float* __restrict__ As, float acc[4][4]) {
    const int lane = threadIdx.x & 31, warp = threadIdx.x >> 5;
    const int r0 = (warp & 3) * 16 + (lane >> 2);
    const int c0 = (warp >> 2) * 32 + 2 * (lane & 3);
#pragma unroll
    for (int j = 0; j < 4; j++) {
        int c = c0 + 8 * j;
        As[r0 * SA + c]           = tf(acc[j][0]);
        As[r0 * SA + c + 1]       = tf(acc[j][1]);
        As[(r0 + 8) * SA + c]     = tf(acc[j][2]);
        As[(r0 + 8) * SA + c + 1] = tf(acc[j][3]);
    }
}
__device__ __forceinline__ void zero4(float a[4][4]) {
#pragma unroll
    for (int j = 0; j < 4; j++)
#pragma unroll
        for (int r = 0; r < 4; r++) a[j][r] = 0.0f;
}

// ---------------- kernels (ALL: 512 threads, SZB dynamic smem) -------------

// part[chunk,b] slab = (Zc^T)_slab @ Zc      grid (16, 8, 2)
__global__ __launch_bounds__(512) void k_g0(const float* __restrict__ Z,
                                            float* __restrict__ part) {
    extern __shared__ float sm[];
    float* As = sm; float* Bs = sm + 64 * SA;
    int chunk = blockIdx.x, b = blockIdx.y, mh = blockIdx.z;
    const float* Zc = Z + (b * NN + chunk * 128) * 128;
    fillAT64(Zc, 128, mh * 64, As);
    fillB(Zc, 128, Bs);
    __syncthreads();
    float acc[4][4]; zero4(acc);
    compute64(As, Bs, acc);
    epi64(part + (chunk * BB + b) * MAT + mh * 64 * 128, 0, 0, 0, 0, acc);
}

// G[0] = sum over 16 chunks        grid (256)
__global__ __launch_bounds__(512) void k_reduce(const float* __restrict__ part,
                                                float* __restrict__ G) {
    int e = blockIdx.x * 512 + threadIdx.x;   // 131072
    int b = e >> 14, i = e & 16383;
    float s = 0.0f;
#pragma unroll
    for (int c = 0; c < 16; c++) s += part[(c * BB + b) * MAT + i];
    G[e] = s;
}

// fused T = Q@G, W = T@V^T (sequential B refill)   grid (8, 8, 2)
__global__ __launch_bounds__(512) void k_TW(const float* __restrict__ q,
                                            const float* __restrict__ v,
                                            const float* __restrict__ G,
                                            float* __restrict__ Wp, int l) {
    extern __shared__ float sm[];
    float* As = sm; float* Bs = sm + 64 * SA;
    int j = blockIdx.x, b = blockIdx.y, mh = blockIdx.z;
    fillA64(q + (l * NH + j) * MAT + mh * 64 * 128, 128, As);
    fillB(G + b * MAT, 128, Bs);
    __syncthreads();
    float acc[4][4]; zero4(acc);
    compute64(As, Bs, acc);
    __syncthreads();                 // GEMM1 reads of As/Bs complete
    storeT64(As, acc);
    fillBT(v + (l * NH + j) * MAT, 128, Bs);
    __syncthreads();
    zero4(acc);
    compute64(As, Bs, acc);
    epi64(Wp + (b * NH + j) * MAT + mh * 64 * 128, 0, 0, 0, 0, acc);
}

// C1: z=0: U slab = G slab @ W' ;  z=1: R slab update (l==0: R = W')
// grid (2, 8, 2)  (x=mh, y=b, z=which)
__global__ __launch_bounds__(512) void k_C1(const float* __restrict__ G,
                                            float* __restrict__ R,
                                            const float* __restrict__ Wp,
                                            float* __restrict__ U, int l) {
    extern __shared__ float sm[];
    float* As = sm; float* Bs = sm + 64 * SA;
    int mh = blockIdx.x, b = blockIdx.y, which = blockIdx.z;
    const float* Wpb = Wp + b * NH * MAT;
    if (which == 1 && l == 0) {
        // R slab = SCALE * sum_j Wp (exact fp32)
#pragma unroll
        for (int i = 0; i < 16; i++) {
            int e = i * 512 + threadIdx.x;            // 8192 per slab
            int idx = mh * 8192 + e;
            float s = 0.0f;
#pragma unroll
            for (int j = 0; j < 8; j++) s += Wpb[j * MAT + idx];
            R[b * MAT + idx] = s * SCALE;
        }
        return;
    }
    const float* Ap = (which ? R : G) + b * MAT + mh * 64 * 128;
    fillA64(Ap, 128, As);
    fillB_ws(Wpb, Bs);
    __syncthreads();
    float acc[4][4]; zero4(acc);
    compute64(As, Bs, acc);
    if (which)  // R = R + W' + R@W'   (W' add from smem, tf32-rounded)
        epi64(R + b * MAT + mh * 64 * 128,
              R + b * MAT + mh * 64 * 128, 0, Bs, mh * 64, acc);
    else
        epi64(U + b * MAT + mh * 64 * 128, 0, 0, 0, 0, acc);
}

// C2: Gnext slab = W'^T slab @ (G+U) + G + U      grid (2, 8)
__global__ __launch_bounds__(512) void k_C2(const float* __restrict__ Wp,
                                            const float* __restrict__ G,
                                            const float* __restrict__ U,
                                            float* __restrict__ Gn) {
    extern __shared__ float sm[];
    float* As = sm; float* Bs = sm + 64 * SA;
    int mh = blockIdx.x, b = blockIdx.y;
    fillAT64_ws(Wp + b * NH * MAT, mh * 64, As);
    fillB2(G + b * MAT, U + b * MAT, Bs);
    __syncthreads();
    float acc[4][4]; zero4(acc);
    compute64(As, Bs, acc);
    epi64(Gn + b * MAT + mh * 64 * 128,
          G  + b * MAT + mh * 64 * 128,
          U  + b * MAT + mh * 64 * 128, 0, 0, acc);
}

// out tile: Y = Zt + Zt@R2 (exact in regs), out = Y + Y@W'3   grid (32, 8)
__global__ __launch_bounds__(512) void k_out(const float* __restrict__ Z,
                                             const float* __restrict__ R,
                                             const float* __restrict__ Wp,
                                             float* __restrict__ out) {
    extern __shared__ float sm[];
    float* As = sm; float* Bs = sm + 64 * SA;
    int tile = blockIdx.x, b = blockIdx.y;
    const float* Zt = Z + (b * NN + tile * 64) * 128;
    fillA64(Zt, 128, As);
    fillB(R + b * MAT, 128, Bs);
    __syncthreads();
    float acc[4][4]; zero4(acc);
    compute64(As, Bs, acc);

    // Y exact = Zt + Zt@R2 at this thread's coords
    const int lane = threadIdx.x & 31, warp = threadIdx.x >> 5;
    const int r0 = (warp & 3) * 16 + (lane >> 2);
    const int c0 = (warp >> 2) * 32 + 2 * (lane & 3);
    float Y[4][4];
#pragma unroll
    for (int j = 0; j < 4; j++) {
        int c = c0 + 8 * j;
        Y[j][0] = acc[j][0] + Zt[r0 * 128 + c];
        Y[j][1] = acc[j][1] + Zt[r0 * 128 + c + 1];
        Y[j][2] = acc[j][2] + Zt[(r0 + 8) * 128 + c];
        Y[j][3] = acc[j][3] + Zt[(r0 + 8) * 128 + c + 1];
    }
    __syncthreads();                 // GEMM1 reads complete
    storeT64(As, Y);                 // As <- tf(Y)
    fillB_ws(Wp + b * NH * MAT, Bs); // Bs <- W'_3
    __syncthreads();
    float acc2[4][4]; zero4(acc2);
    compute64(As, Bs, acc2);

    float* Ct = out + (b * NN + tile * 64) * 128;
#pragma unroll
    for (int j = 0; j < 4; j++) {
        int c = c0 + 8 * j;
        *(float2*)(Ct + r0 * 128 + c) =
            make_float2(Y[j][0] + acc2[j][0], Y[j][1] + acc2[j][1]);
        *(float2*)(Ct + (r0 + 8) * 128 + c) =
            make_float2(Y[j][2] + acc2[j][2], Y[j][3] + acc2[j][3]);
    }
}

// ---------------- host ----------------
extern "C" void kernel_launch(void* const* d_in, const int* in_sizes, int n_in,
                              void* d_out, int out_size) {
    const float* Z = (const float*)d_in[0];
    const float* v = (const float*)d_in[1];
    const float* q = (const float*)d_in[2];
    float* out = (float*)d_out;

    cudaFuncSetAttribute(k_g0,     cudaFuncAttributeMaxDynamicSharedMemorySize, SZB);
    cudaFuncSetAttribute(k_reduce, cudaFuncAttributeMaxDynamicSharedMemorySize, SZB);
    cudaFuncSetAttribute(k_TW,     cudaFuncAttributeMaxDynamicSharedMemorySize, SZB);
    cudaFuncSetAttribute(k_C1,     cudaFuncAttributeMaxDynamicSharedMemorySize, SZB);
    cudaFuncSetAttribute(k_C2,     cudaFuncAttributeMaxDynamicSharedMemorySize, SZB);
    cudaFuncSetAttribute(k_out,    cudaFuncAttributeMaxDynamicSharedMemorySize, SZB);

    float *pPart, *pG, *pR, *pWp, *pU;
    cudaGetSymbolAddress((void**)&pPart, g_part);
    cudaGetSymbolAddress((void**)&pG,  g_G);
    cudaGetSymbolAddress((void**)&pR,  g_R);
    cudaGetSymbolAddress((void**)&pWp, g_Wp);
    cudaGetSymbolAddress((void**)&pU,  g_U);

    float* Gbuf[2] = { pG, pG + BB * MAT };

    k_g0    <<<dim3(16, BB, 2), 512, SZB>>>(Z, pPart);
    k_reduce<<<256, 512, SZB>>>(pPart, Gbuf[0]);

    int cur = 0;
    for (int l = 0; l < 4; l++) {
        k_TW<<<dim3(NH, BB, 2), 512, SZB>>>(q, v, Gbuf[cur], pWp, l);
        if (l < 3) {
            k_C1<<<dim3(2, BB, 2), 512, SZB>>>(Gbuf[cur], pR, pWp, pU, l);
            k_C2<<<dim3(2, BB), 512, SZB>>>(pWp, Gbuf[cur], pU, Gbuf[cur ^ 1]);
            cur ^= 1;
        }
    }

    k_out<<<dim3(32, BB), 512, SZB>>>(Z, pR, pWp, out);
}

// round 10
// speedup vs baseline: 1.7155x; 1.1304x over previous
#include <cuda_runtime.h>

#define BB 8
#define NN 2048
#define NH 8
#define MAT 16384
#define SCALE (1.0f/16384.0f)   // 1/(N*NH)
#define SA  132                 // A smem row stride (floats)
#define SBN 136                 // B smem row stride (floats)
#define SZB ((64 * SA + 128 * SBN) * 4)   // 103424 B — uniform for all GEMM kernels
#define NT  256                 // threads per block (8 warps)

// ---------------- scratch (device globals) ----------------
__device__ __align__(16) float g_part[16 * BB * MAT];
__device__ __align__(16) float g_G[2][BB * MAT];
__device__ __align__(16) float g_R [BB * MAT];
__device__ __align__(16) float g_Wp[BB * NH * MAT];
__device__ __align__(16) float g_Wq[BB * MAT];
__device__ __align__(16) float g_U [BB * MAT];

// ---------------- tf32 helpers ----------------
__device__ __forceinline__ float tf(float x) {
    float y; asm("cvt.rna.tf32.f32 %0, %1;" : "=f"(y) : "f"(x)); return y;
}
__device__ __forceinline__ float4 tf4(float4 x) {
    x.x = tf(x.x); x.y = tf(x.y); x.z = tf(x.z); x.w = tf(x.w); return x;
}
__device__ __forceinline__ void mma8(float c[4], const float a[4], const float b[2]) {
    asm volatile(
        "mma.sync.aligned.m16n8k8.row.col.f32.tf32.tf32.f32 "
        "{%0,%1,%2,%3}, {%4,%5,%6,%7}, {%8,%9}, {%0,%1,%2,%3};"
        : "+f"(c[0]), "+f"(c[1]), "+f"(c[2]), "+f"(c[3])
        : "r"(__float_as_uint(a[0])), "r"(__float_as_uint(a[1])),
          "r"(__float_as_uint(a[2])), "r"(__float_as_uint(a[3])),
          "r"(__float_as_uint(b[0])), "r"(__float_as_uint(b[1])));
}

// ---------------- smem fills (256 threads) ----------------
// As[m][k] = tf(A[m*lda + k]), 64 rows x 128
__device__ __forceinline__ void fillA64(const float* __restrict__ A, int lda,
                                        float* __restrict__ As) {
#pragma unroll
    for (int i = 0; i < 8; i++) {
        int idx = threadIdx.x + NT * i;          // 2048 float4
        int m = idx >> 5, kf = (idx & 31) * 4;
        *(float4*)(As + m * SA + kf) = tf4(*(const float4*)(A + m * lda + kf));
    }
}
// As[m][k] = tf(A[k*lda + moff + m])   (transposed source, 64 rows)
__device__ __forceinline__ void fillAT64(const float* __restrict__ A, int lda,
                                         int moff, float* __restrict__ As) {
#pragma unroll
    for (int i = 0; i < 8; i++) {
        int idx = threadIdx.x + NT * i;          // 2048 float4
        int k = idx >> 4, mf = (idx & 15) * 4;
        float4 x = tf4(*(const float4*)(A + k * lda + moff + mf));
        As[(mf + 0) * SA + k] = x.x;
        As[(mf + 1) * SA + k] = x.y;
        As[(mf + 2) * SA + k] = x.z;
        As[(mf + 3) * SA + k] = x.w;
    }
}
// Bs[k][n] = tf(B[k*ldb + n]), 128x128
__device__ __forceinline__ void fillB(const float* __restrict__ B, int ldb,
                                      float* __restrict__ Bs) {
#pragma unroll
    for (int i = 0; i < 16; i++) {
        int idx = threadIdx.x + NT * i;          // 4096 float4
        int k = idx >> 5, nf = (idx & 31) * 4;
        *(float4*)(Bs + k * SBN + nf) = tf4(*(const float4*)(B + k * ldb + nf));
    }
}
// Bs[k][n] = tf(B1[k*128+n] + B2[k*128+n])
__device__ __forceinline__ void fillB2(const float* __restrict__ B1,
                                       const float* __restrict__ B2,
                                       float* __restrict__ Bs) {
#pragma unroll
    for (int i = 0; i < 16; i++) {
        int idx = threadIdx.x + NT * i;
        int k = idx >> 5, nf = (idx & 31) * 4;
        float4 x = *(const float4*)(B1 + k * 128 + nf);
        float4 y = *(const float4*)(B2 + k * 128 + nf);
        x.x += y.x; x.y += y.y; x.z += y.z; x.w += y.w;
        *(float4*)(Bs + k * SBN + nf) = tf4(x);
    }
}
// Bs[k][n] = tf(B[n*ldb + k])   (transposed: V^T)
__device__ __forceinline__ void fillBT(const float* __restrict__ B, int ldb,
                                       float* __restrict__ Bs) {
#pragma unroll
    for (int i = 0; i < 16; i++) {
        int idx = threadIdx.x + NT * i;
        int n = idx >> 5, kf = (idx & 31) * 4;
        float4 x = tf4(*(const float4*)(B + n * ldb + kf));
        Bs[(kf + 0) * SBN + n] = x.x;
        Bs[(kf + 1) * SBN + n] = x.y;
        Bs[(kf + 2) * SBN + n] = x.z;
        Bs[(kf + 3) * SBN + n] = x.w;
    }
}

// ---------------- compute core: 64x128 tile, K=128, 8 warps of 32x32 ------
__device__ __forceinline__ void compute64(const float* __restrict__ As,
                                          const float* __restrict__ Bs,
                                          float acc[2][4][4]) {
    const int lane = threadIdx.x & 31, warp = threadIdx.x >> 5;
    const int mr = (warp & 1) * 32, nc = (warp >> 1) * 32;
    const int ar = lane >> 2, ac = lane & 3;
    const int bk = lane & 3,  bn = lane >> 2;
#pragma unroll
    for (int kk = 0; kk < 128; kk += 8) {
        float a[2][4];
#pragma unroll
        for (int i = 0; i < 2; i++) {
            const float* p = As + (mr + 16 * i + ar) * SA + kk + ac;
            a[i][0] = p[0]; a[i][1] = p[8 * SA]; a[i][2] = p[4]; a[i][3] = p[8 * SA + 4];
        }
#pragma unroll
        for (int j = 0; j < 4; j++) {
            const float* qp = Bs + (kk + bk) * SBN + nc + 8 * j + bn;
            float b[2] = { qp[0], qp[4 * SBN] };
            mma8(acc[0][j], a[0], b);
            mma8(acc[1][j], a[1], b);
        }
    }
}
__device__ __forceinline__ void zacc(float a[2][4][4]) {
#pragma unroll
    for (int i = 0; i < 2; i++)
#pragma unroll
        for (int j = 0; j < 4; j++)
#pragma unroll
            for (int r = 0; r < 4; r++) a[i][j][r] = 0.0f;
}

// ---------------- epilogue: 64x128, adds up to two fp32 sources -----------
__device__ __forceinline__ void epi64(float* __restrict__ C,
                                      const float* __restrict__ a1,
                                      const float* __restrict__ a2,
                                      float acc[2][4][4]) {
    const int lane = threadIdx.x & 31, warp = threadIdx.x >> 5;
    const int r0 = (warp & 1) * 32 + (lane >> 2);
    const int c0 = (warp >> 1) * 32 + 2 * (lane & 3);
#pragma unroll
    for (int i = 0; i < 2; i++)
#pragma unroll
        for (int j = 0; j < 4; j++) {
            int r = r0 + 16 * i, c = c0 + 8 * j;
            float2 lo = make_float2(acc[i][j][0], acc[i][j][1]);
            float2 hi = make_float2(acc[i][j][2], acc[i][j][3]);
            if (a1) {
                float2 x = *(const float2*)(a1 + r * 128 + c);
                float2 y = *(const float2*)(a1 + (r + 8) * 128 + c);
                lo.x += x.x; lo.y += x.y; hi.x += y.x; hi.y += y.y;
            }
            if (a2) {
                float2 x = *(const float2*)(a2 + r * 128 + c);
                float2 y = *(const float2*)(a2 + (r + 8) * 128 + c);
                lo.x += x.x; lo.y += x.y; hi.x += y.x; hi.y += y.y;
            }
            *(float2*)(C + r * 128 + c)       = lo;
            *(float2*)(C + (r + 8) * 128 + c) = hi;
        }
}
// acc (64x128 warp-tiled) -> As simple layout (tf32), for chained GEMM
__device__ __forceinline__ void storeT64(float* __restrict__ As,
                                         float acc[2][4][4]) {
    const int lane = threadIdx.x & 31, warp = threadIdx.x >> 5;
    const int r0 = (warp & 1) * 32 + (lane >> 2);
    const int c0 = (warp >> 1) * 32 + 2 * (lane & 3);
#pragma unroll
    for (int i = 0; i < 2; i++)
#pragma unroll
        for (int j = 0; j < 4; j++) {
            int r = r0 + 16 * i, c = c0 + 8 * j;
            As[r * SA + c]           = tf(acc[i][j][0]);
            As[r * SA + c + 1]       = tf(acc[i][j][1]);
            As[(r + 8) * SA + c]     = tf(acc[i][j][2]);
            As[(r + 8) * SA + c + 1] = tf(acc[i][j][3]);
        }
}

// ---------------- kernels ----------------

// part[chunk,b] slab = (Zc^T)_slab @ Zc      grid (16, 8, 2)
__global__ __launch_bounds__(NT) void k_g0(const float* __restrict__ Z,
                                           float* __restrict__ part) {
    extern __shared__ float sm[];
    float* As = sm; float* Bs = sm + 64 * SA;
    int chunk = blockIdx.x, b = blockIdx.y, mh = blockIdx.z;
    const float* Zc = Z + (b * NN + chunk * 128) * 128;
    fillAT64(Zc, 128, mh * 64, As);
    fillB(Zc, 128, Bs);
    __syncthreads();
    float acc[2][4][4]; zacc(acc);
    compute64(As, Bs, acc);
    epi64(part + (chunk * BB + b) * MAT + mh * 64 * 128, 0, 0, acc);
}

// G[0] = sum over 16 chunks        grid (512) x 256 thr (scalar)
__global__ __launch_bounds__(NT) void k_reduce(const float* __restrict__ part,
                                               float* __restrict__ G) {
    int e = blockIdx.x * NT + threadIdx.x;   // 131072
    int b = e >> 14, i = e & 16383;
    float s = 0.0f;
#pragma unroll
    for (int c = 0; c < 16; c++) s += part[(c * BB + b) * MAT + i];
    G[e] = s;
}

// fused T = Q@G, W = T@V^T (sequential B refill)   grid (8, 8, 2)
__global__ __launch_bounds__(NT) void k_TW(const float* __restrict__ q,
                                           const float* __restrict__ v,
                                           const float* __restrict__ G,
                                           float* __restrict__ Wp, int l) {
    extern __shared__ float sm[];
    float* As = sm; float* Bs = sm + 64 * SA;
    int j = blockIdx.x, b = blockIdx.y, mh = blockIdx.z;
    fillA64(q + (l * NH + j) * MAT + mh * 64 * 128, 128, As);
    fillB(G + b * MAT, 128, Bs);
    __syncthreads();
    float acc[2][4][4]; zacc(acc);
    compute64(As, Bs, acc);
    __syncthreads();                 // GEMM1 reads of As/Bs complete
    storeT64(As, acc);
    fillBT(v + (l * NH + j) * MAT, 128, Bs);
    __syncthreads();
    zacc(acc);
    compute64(As, Bs, acc);
    epi64(Wp + (b * NH + j) * MAT + mh * 64 * 128, 0, 0, acc);
}

// W'[b] = SCALE * sum_j Wp[b,j]  (float4); layer 0 also R = W'   grid (128)
__global__ __launch_bounds__(NT) void k_Wsum(const float* __restrict__ Wp,
                                             float* __restrict__ Wq,
                                             float* __restrict__ R, int copyR) {
    int e = (blockIdx.x * NT + threadIdx.x) * 4;   // 131072 floats
    int b = e >> 14, i = e & 16383;
    float4 s = make_float4(0.f, 0.f, 0.f, 0.f);
#pragma unroll
    for (int j = 0; j < NH; j++) {
        float4 x = *(const float4*)(Wp + (b * NH + j) * MAT + i);
        s.x += x.x; s.y += x.y; s.z += x.z; s.w += x.w;
    }
    s.x *= SCALE; s.y *= SCALE; s.z *= SCALE; s.w *= SCALE;
    *(float4*)(Wq + e) = s;
    if (copyR) *(float4*)(R + e) = s;
}

// C1: z=0: U slab = G slab @ W' ;  z=1 (l>0): R slab = R + W' + R@W'
// grid (2, 8, zz)
__global__ __launch_bounds__(NT) void k_C1(const float* __restrict__ G,
                                           float* __restrict__ R,
                                           const float* __restrict__ Wq,
                                           float* __restrict__ U) {
    extern __shared__ float sm[];
    float* As = sm; float* Bs = sm + 64 * SA;
    int mh = blockIdx.x, b = blockIdx.y, which = blockIdx.z;
    const float* Ap = (which ? R : G) + b * MAT + mh * 64 * 128;
    fillA64(Ap, 128, As);
    fillB(Wq + b * MAT, 128, Bs);
    __syncthreads();
    float acc[2][4][4]; zacc(acc);
    compute64(As, Bs, acc);
    if (which) epi64(R + b * MAT + mh * 64 * 128,
                     R  + b * MAT + mh * 64 * 128,
                     Wq + b * MAT + mh * 64 * 128, acc);
    else       epi64(U + b * MAT + mh * 64 * 128, 0, 0, acc);
}

// C2: Gnext slab = W'^T slab @ (G+U) + G + U      grid (2, 8)
__global__ __launch_bounds__(NT) void k_C2(const float* __restrict__ Wq,
                                           const float* __restrict__ G,
                                           const float* __restrict__ U,
                                           float* __restrict__ Gn) {
    extern __shared__ float sm[];
    float* As = sm; float* Bs = sm + 64 * SA;
    int mh = blockIdx.x, b = blockIdx.y;
    fillAT64(Wq + b * MAT, 128, mh * 64, As);
    fillB2(G + b * MAT, U + b * MAT, Bs);
    __syncthreads();
    float acc[2][4][4]; zacc(acc);
    compute64(As, Bs, acc);
    epi64(Gn + b * MAT + mh * 64 * 128,
          G  + b * MAT + mh * 64 * 128,
          U  + b * MAT + mh * 64 * 128, acc);
}

// out tile: Y = Zt + Zt@R2 (exact in regs), out = Y + Y@W'3   grid (32, 8)
__global__ __launch_bounds__(NT) void k_out(const float* __restrict__ Z,
                                            const float* __restrict__ R,
                                            const float* __restrict__ Wq,
                                            float* __restrict__ out) {
    extern __shared__ float sm[];
    float* As = sm; float* Bs = sm + 64 * SA;
    int tile = blockIdx.x, b = blockIdx.y;
    const float* Zt = Z + (b * NN + tile * 64) * 128;
    fillA64(Zt, 128, As);
    fillB(R + b * MAT, 128, Bs);
    __syncthreads();
    float acc[2][4][4]; zacc(acc);
    compute64(As, Bs, acc);

    // Y exact = Zt + Zt@R2 at this thread's coords
    const int lane = threadIdx.x & 31, warp = threadIdx.x >> 5;
    const int r0 = (warp & 1) * 32 + (lane >> 2);
    const int c0 = (warp >> 1) * 32 + 2 * (lane & 3);
    float Y[2][4][4];
#pragma unroll
    for (int i = 0; i < 2; i++)
#pragma unroll
        for (int j = 0; j < 4; j++) {
            int r = r0 + 16 * i, c = c0 + 8 * j;
            Y[i][j][0] = acc[i][j][0] + Zt[r * 128 + c];
            Y[i][j][1] = acc[i][j][1] + Zt[r * 128 + c + 1];
            Y[i][j][2] = acc[i][j][2] + Zt[(r + 8) * 128 + c];
            Y[i][j][3] = acc[i][j][3] + Zt[(r + 8) * 128 + c + 1];
        }
    __syncthreads();                 // GEMM1 reads complete
    storeT64(As, Y);                 // As <- tf(Y)
    fillB(Wq + b * MAT, 128, Bs);    // Bs <- W'_3
    __syncthreads();
    float acc2[2][4][4]; zacc(acc2);
    compute64(As, Bs, acc2);

    float* Ct = out + (b * NN + tile * 64) * 128;
#pragma unroll
    for (int i = 0; i < 2; i++)
#pragma unroll
        for (int j = 0; j < 4; j++) {
            int r = r0 + 16 * i, c = c0 + 8 * j;
            *(float2*)(Ct + r * 128 + c) =
                make_float2(Y[i][j][0] + acc2[i][j][0], Y[i][j][1] + acc2[i][j][1]);
            *(float2*)(Ct + (r + 8) * 128 + c) =
                make_float2(Y[i][j][2] + acc2[i][j][2], Y[i][j][3] + acc2[i][j][3]);
        }
}

// ---------------- host ----------------
extern "C" void kernel_launch(void* const* d_in, const int* in_sizes, int n_in,
                              void* d_out, int out_size) {
    const float* Z = (const float*)d_in[0];
    const float* v = (const float*)d_in[1];
    const float* q = (const float*)d_in[2];
    float* out = (float*)d_out;

    cudaFuncSetAttribute(k_g0,  cudaFuncAttributeMaxDynamicSharedMemorySize, SZB);
    cudaFuncSetAttribute(k_TW,  cudaFuncAttributeMaxDynamicSharedMemorySize, SZB);
    cudaFuncSetAttribute(k_C1,  cudaFuncAttributeMaxDynamicSharedMemorySize, SZB);
    cudaFuncSetAttribute(k_C2,  cudaFuncAttributeMaxDynamicSharedMemorySize, SZB);
    cudaFuncSetAttribute(k_out, cudaFuncAttributeMaxDynamicSharedMemorySize, SZB);

    float *pPart, *pG, *pR, *pWp, *pWq, *pU;
    cudaGetSymbolAddress((void**)&pPart, g_part);
    cudaGetSymbolAddress((void**)&pG,  g_G);
    cudaGetSymbolAddress((void**)&pR,  g_R);
    cudaGetSymbolAddress((void**)&pWp, g_Wp);
    cudaGetSymbolAddress((void**)&pWq, g_Wq);
    cudaGetSymbolAddress((void**)&pU,  g_U);

    float* Gbuf[2] = { pG, pG + BB * MAT };

    k_g0    <<<dim3(16, BB, 2), NT, SZB>>>(Z, pPart);
    k_reduce<<<512, NT>>>(pPart, Gbuf[0]);

    int cur = 0;
    for (int l = 0; l < 4; l++) {
        k_TW  <<<dim3(NH, BB, 2), NT, SZB>>>(q, v, Gbuf[cur], pWp, l);
        k_Wsum<<<128, NT>>>(pWp, pWq, pR, l == 0 ? 1 : 0);
        if (l < 3) {
            int zz = (l == 0) ? 1 : 2;
            k_C1<<<dim3(2, BB, zz), NT, SZB>>>(Gbuf[cur], pR, pWq, pU);
            k_C2<<<dim3(2, BB), NT, SZB>>>(pWq, Gbuf[cur], pU, Gbuf[cur ^ 1]);
            cur ^= 1;
        }
    }

    k_out<<<dim3(32, BB), NT, SZB>>>(Z, pR, pWq, out);
}